// round 4
// baseline (speedup 1.0000x reference)
#include <cuda_runtime.h>
#include <math.h>
#include <float.h>

#define NN 100000
#define EE 1600000
#define IN_F 256
#define HH 4
#define DD 32
#define CC 47
#define HD 128        // H*D
#define HC 188        // H*C
#define NEG_SLOPE 0.2f

// ---------------- scratch (static device globals; no allocation) ------------
__device__ float g_feat[(size_t)NN * HC];   // per-layer feature (max H*C)
__device__ float g_acc [(size_t)NN * HC];   // aggregation accumulator
__device__ float g_hbuf[(size_t)NN * HD];   // hidden features between layers
__device__ float g_ebuf[(size_t)EE * HH];   // per-edge logits / exp
__device__ float g_el[NN * HH];
__device__ float g_er[NN * HH];
__device__ float g_m [NN * HH];
__device__ float g_den[NN * HH];

// ---------------- SGEMM: g_feat[M,Kn] = A[M,K] @ B[K,Kn] --------------------
// 64x64 tile, BK=16, 256 threads, 4x4 micro-tile per thread.
// A operand selected in DEVICE code: use_hbuf ? g_hbuf : Aext.
#define BM 64
#define BN 64
#define BK 16

__global__ void sgemm_kernel(const float* __restrict__ Aext,
                             const float* __restrict__ B,
                             int M, int K, int Kn, int use_hbuf) {
    __shared__ float As[BK][BM + 1];
    __shared__ float Bs[BK][BN];
    const float* __restrict__ A = use_hbuf ? (const float*)g_hbuf : Aext;
    float* __restrict__ C = g_feat;

    int tid = threadIdx.x;              // 0..255
    int row0 = blockIdx.y * BM;
    int col0 = blockIdx.x * BN;
    int tx = tid & 15;                  // 0..15
    int ty = tid >> 4;                  // 0..15

    int a_m = tid >> 2;
    int a_k = (tid & 3) << 2;
    int b_k = tid >> 4;
    int b_n = (tid & 15) << 2;

    float acc[4][4];
#pragma unroll
    for (int i = 0; i < 4; i++)
#pragma unroll
        for (int j = 0; j < 4; j++) acc[i][j] = 0.f;

    for (int k0 = 0; k0 < K; k0 += BK) {
        float4 av = make_float4(0.f, 0.f, 0.f, 0.f);
        if (row0 + a_m < M)
            av = *(const float4*)(A + (size_t)(row0 + a_m) * K + k0 + a_k);
        As[a_k + 0][a_m] = av.x;
        As[a_k + 1][a_m] = av.y;
        As[a_k + 2][a_m] = av.z;
        As[a_k + 3][a_m] = av.w;

        float4 bv = make_float4(0.f, 0.f, 0.f, 0.f);
        int bc = col0 + b_n;
        if (bc < Kn)
            bv = *(const float4*)(B + (size_t)(k0 + b_k) * Kn + bc);
        *(float4*)&Bs[b_k][b_n] = bv;

        __syncthreads();

#pragma unroll
        for (int k = 0; k < BK; k++) {
            float ar[4], br[4];
#pragma unroll
            for (int i = 0; i < 4; i++) ar[i] = As[k][ty * 4 + i];
#pragma unroll
            for (int j = 0; j < 4; j++) br[j] = Bs[k][tx * 4 + j];
#pragma unroll
            for (int i = 0; i < 4; i++)
#pragma unroll
                for (int j = 0; j < 4; j++)
                    acc[i][j] = fmaf(ar[i], br[j], acc[i][j]);
        }
        __syncthreads();
    }

    int col = col0 + tx * 4;
#pragma unroll
    for (int i = 0; i < 4; i++) {
        int row = row0 + ty * 4 + i;
        if (row < M && col < Kn) {
            float4 v = make_float4(acc[i][0], acc[i][1], acc[i][2], acc[i][3]);
            *(float4*)(C + (size_t)row * Kn + col) = v;
        }
    }
}

// ---------------- per-node attention projections (el, er) -------------------
// one warp per node; F = 32 or 47
__global__ void elr_kernel(const float* __restrict__ al,
                           const float* __restrict__ ar,
                           int F) {
    int w = (blockIdx.x * blockDim.x + threadIdx.x) >> 5;
    int lane = threadIdx.x & 31;
    if (w >= NN) return;
    const float* frow = g_feat + (size_t)w * HH * F;
#pragma unroll
    for (int h = 0; h < HH; h++) {
        float sl = 0.f, sr = 0.f;
        for (int d = lane; d < F; d += 32) {
            float f = frow[h * F + d];
            sl = fmaf(f, al[h * F + d], sl);
            sr = fmaf(f, ar[h * F + d], sr);
        }
#pragma unroll
        for (int o = 16; o; o >>= 1) {
            sl += __shfl_xor_sync(0xffffffffu, sl, o);
            sr += __shfl_xor_sync(0xffffffffu, sr, o);
        }
        if (lane == 0) {
            g_el[w * HH + h] = sl;
            g_er[w * HH + h] = sr;
        }
    }
}

// ---------------- init accumulators -----------------------------------------
__global__ void init_kernel(int HF) {
    long i = (long)blockIdx.x * blockDim.x + threadIdx.x;
    if (i < (long)NN * HF) g_acc[i] = 0.f;
    if (i < (long)NN * HH) { g_m[i] = -FLT_MAX; g_den[i] = 0.f; }
}

// ---------------- edge stage 1: logits + segment max ------------------------
__global__ void edge_e_kernel(const int* __restrict__ src,
                              const int* __restrict__ dst) {
    int i = blockIdx.x * blockDim.x + threadIdx.x;   // over E*H
    if (i >= EE * HH) return;
    int e = i >> 2, h = i & 3;
    int s = src[e], d = dst[e];
    float v = g_el[s * HH + h] + g_er[d * HH + h];
    v = v > 0.f ? v : NEG_SLOPE * v;
    g_ebuf[i] = v;
    float* addr = &g_m[d * HH + h];
    if (v >= 0.f) atomicMax((int*)addr, __float_as_int(v));
    else          atomicMin((unsigned int*)addr, __float_as_uint(v));
}

// ---------------- edge stage 2: exp + segment sum ---------------------------
__global__ void edge_exp_kernel(const int* __restrict__ dst) {
    int i = blockIdx.x * blockDim.x + threadIdx.x;
    if (i >= EE * HH) return;
    int e = i >> 2, h = i & 3;
    int d = dst[e];
    float ex = expf(g_ebuf[i] - g_m[d * HH + h]);
    g_ebuf[i] = ex;
    atomicAdd(&g_den[d * HH + h], ex);
}

// ---------------- edge stage 3: weighted scatter aggregation ----------------
// alpha = ebuf / den[dst] computed inline (den is L2-resident, 1.6MB).
// F = 32 path (layers 1, 2): one float4 per thread, 4 scalar REDs.
__global__ void edge_aggr32_kernel(const int* __restrict__ src,
                                   const int* __restrict__ dst) {
    int i = blockIdx.x * blockDim.x + threadIdx.x;   // over E*H*8
    if (i >= EE * HH * 8) return;
    int v = i & 7;
    int h = (i >> 3) & 3;
    int e = i >> 5;
    int s = src[e], d = dst[e];
    float a = g_ebuf[e * HH + h] / g_den[d * HH + h];
    float4 f = *(const float4*)(g_feat + ((size_t)s * HH + h) * DD + v * 4);
    float* p = g_acc + ((size_t)d * HH + h) * DD + v * 4;
    atomicAdd(p + 0, a * f.x);
    atomicAdd(p + 1, a * f.y);
    atomicAdd(p + 2, a * f.z);
    atomicAdd(p + 3, a * f.w);
}

// F = 47 path (layer 3): scalar per element.
__global__ void edge_aggr47_kernel(const int* __restrict__ src,
                                   const int* __restrict__ dst) {
    unsigned int i = blockIdx.x * blockDim.x + threadIdx.x;  // over E*HC
    if (i >= (unsigned int)EE * HC) return;
    unsigned int e = i / HC;
    unsigned int r = i - e * HC;
    unsigned int h = r / CC;
    unsigned int c = r - h * CC;
    int s = src[e], d = dst[e];
    float a = g_ebuf[e * HH + h] / g_den[d * HH + h];
    float val = a * g_feat[(size_t)s * HC + h * CC + c];
    atomicAdd(&g_acc[(size_t)d * HC + h * CC + c], val);
}

// ---------------- bias + ReLU into hidden buffer ----------------------------
__global__ void bias_relu_kernel(const float* __restrict__ b) {
    int i = blockIdx.x * blockDim.x + threadIdx.x;
    if (i >= NN * HD) return;
    g_hbuf[i] = fmaxf(g_acc[i] + b[i & (HD - 1)], 0.f);
}

// ---------------- final: bias + head mean + log_softmax ---------------------
__global__ void final_kernel(const float* __restrict__ b3,
                             float* __restrict__ out) {
    int w = (blockIdx.x * blockDim.x + threadIdx.x) >> 5;
    int lane = threadIdx.x & 31;
    if (w >= NN) return;
    int c0 = lane, c1 = lane + 32;
    float v0 = 0.f, v1 = 0.f;
#pragma unroll
    for (int h = 0; h < HH; h++) {
        const float* row = g_acc + (size_t)w * HC + h * CC;
        if (c0 < CC) v0 += row[c0] + b3[h * CC + c0];
        if (c1 < CC) v1 += row[c1] + b3[h * CC + c1];
    }
    v0 *= (1.f / HH);
    v1 *= (1.f / HH);
    float m0 = (c0 < CC) ? v0 : -FLT_MAX;
    float m1 = (c1 < CC) ? v1 : -FLT_MAX;
    float mm = fmaxf(m0, m1);
#pragma unroll
    for (int o = 16; o; o >>= 1) mm = fmaxf(mm, __shfl_xor_sync(0xffffffffu, mm, o));
    float s = 0.f;
    if (c0 < CC) s += expf(v0 - mm);
    if (c1 < CC) s += expf(v1 - mm);
#pragma unroll
    for (int o = 16; o; o >>= 1) s += __shfl_xor_sync(0xffffffffu, s, o);
    float lse = logf(s) + mm;
    if (c0 < CC) out[(size_t)w * CC + c0] = v0 - lse;
    if (c1 < CC) out[(size_t)w * CC + c1] = v1 - lse;
}

// ---------------- host orchestration ----------------------------------------
static void run_layer(const float* hin_ext, int use_hbuf, int K,
                      const float* W, const float* al, const float* ar,
                      int F, int HF,
                      const int* src, const int* dst) {
    dim3 ggrid((HF + BN - 1) / BN, (NN + BM - 1) / BM);
    sgemm_kernel<<<ggrid, 256>>>(hin_ext, W, NN, K, HF, use_hbuf);

    elr_kernel<<<(NN * 32 + 255) / 256, 256>>>(al, ar, F);

    init_kernel<<<((long)NN * HF + 255) / 256, 256>>>(HF);

    int eh_blocks = (EE * HH + 255) / 256;
    edge_e_kernel<<<eh_blocks, 256>>>(src, dst);
    edge_exp_kernel<<<eh_blocks, 256>>>(dst);

    if (F == DD) {
        edge_aggr32_kernel<<<(EE * HH * 8 + 255) / 256, 256>>>(src, dst);
    } else {
        edge_aggr47_kernel<<<((unsigned int)EE * HC + 255) / 256, 256>>>(src, dst);
    }
}

extern "C" void kernel_launch(void* const* d_in, const int* in_sizes, int n_in,
                              void* d_out, int out_size) {
    const float* x   = (const float*)d_in[0];
    const int*   src = (const int*)  d_in[1];
    const int*   dst = (const int*)  d_in[2];
    const float* W1  = (const float*)d_in[3];
    const float* al1 = (const float*)d_in[4];
    const float* ar1 = (const float*)d_in[5];
    const float* b1  = (const float*)d_in[6];
    const float* W2  = (const float*)d_in[7];
    const float* al2 = (const float*)d_in[8];
    const float* ar2 = (const float*)d_in[9];
    const float* b2  = (const float*)d_in[10];
    const float* W3  = (const float*)d_in[11];
    const float* al3 = (const float*)d_in[12];
    const float* ar3 = (const float*)d_in[13];
    const float* b3  = (const float*)d_in[14];
    float* out = (float*)d_out;

    // Layer 1: IN -> H*D, ReLU. A = x (external input).
    run_layer(x, 0, IN_F, W1, al1, ar1, DD, HD, src, dst);
    bias_relu_kernel<<<(NN * HD + 255) / 256, 256>>>(b1);

    // Layer 2: H*D -> H*D, ReLU. A = g_hbuf (selected in device code).
    run_layer(nullptr, 1, HD, W2, al2, ar2, DD, HD, src, dst);
    bias_relu_kernel<<<(NN * HD + 255) / 256, 256>>>(b2);

    // Layer 3: H*D -> H*C, no activation; then head-mean + log_softmax.
    run_layer(nullptr, 1, HD, W3, al3, ar3, CC, HC, src, dst);
    final_kernel<<<(NN * 32 + 255) / 256, 256>>>(b3, out);
}

// round 5
// speedup vs baseline: 2.4496x; 2.4496x over previous
#include <cuda_runtime.h>
#include <math.h>
#include <float.h>

#define NN 100000
#define EE 1600000
#define IN_F 256
#define HH 4
#define DD 32
#define CC 47
#define HD 128        // H*D
#define HC 188        // H*C
#define NEG_SLOPE 0.2f
#define FULLMASK 0xffffffffu

// ---------------- scratch (static device globals; no allocation) ------------
__device__ float g_feat[(size_t)NN * HC];   // per-layer feature (max H*C)
__device__ float g_hbuf[(size_t)NN * HD];   // hidden features between layers
__device__ float g_el[NN * HH];
__device__ float g_er[NN * HH];
// CSR by destination
__device__ int g_deg[NN];
__device__ int g_off[NN + 1];
__device__ int g_cur[NN];
__device__ int g_esrc[EE];                  // src node per edge, grouped by dst

// ---------------- warp reduction helpers ------------------------------------
__device__ __forceinline__ float warpmax(float v) {
#pragma unroll
    for (int o = 16; o; o >>= 1) v = fmaxf(v, __shfl_xor_sync(FULLMASK, v, o));
    return v;
}
__device__ __forceinline__ float warpsum(float v) {
#pragma unroll
    for (int o = 16; o; o >>= 1) v += __shfl_xor_sync(FULLMASK, v, o);
    return v;
}
__device__ __forceinline__ float lrelu(float v) {
    return v > 0.f ? v : NEG_SLOPE * v;
}

// ---------------- CSR build --------------------------------------------------
__global__ void zero_deg_kernel() {
    int i = blockIdx.x * blockDim.x + threadIdx.x;
    if (i < NN) g_deg[i] = 0;
}
__global__ void hist_kernel(const int* __restrict__ dst) {
    int e = blockIdx.x * blockDim.x + threadIdx.x;
    if (e < EE) atomicAdd(&g_deg[dst[e]], 1);
}
// single block, 1024 threads: sequential-tile Hillis-Steele scan
__global__ void scan_kernel() {
    __shared__ int sh[1024];
    __shared__ int s_carry;
    int tid = threadIdx.x;
    if (tid == 0) s_carry = 0;
    __syncthreads();
    for (int base = 0; base < NN; base += 1024) {
        int i = base + tid;
        int v = (i < NN) ? g_deg[i] : 0;
        sh[tid] = v;
        __syncthreads();
#pragma unroll
        for (int o = 1; o < 1024; o <<= 1) {
            int t = (tid >= o) ? sh[tid - o] : 0;
            __syncthreads();
            sh[tid] += t;
            __syncthreads();
        }
        int incl = sh[tid];
        int excl = incl - v;
        if (i < NN) {
            g_off[i] = s_carry + excl;
            g_cur[i] = s_carry + excl;
        }
        __syncthreads();
        if (tid == 1023) s_carry += incl;
        __syncthreads();
    }
    if (tid == 0) g_off[NN] = s_carry;
}
__global__ void scatter_kernel(const int* __restrict__ src,
                               const int* __restrict__ dst) {
    int e = blockIdx.x * blockDim.x + threadIdx.x;
    if (e >= EE) return;
    int p = atomicAdd(&g_cur[dst[e]], 1);
    g_esrc[p] = src[e];
}

// ---------------- SGEMM: g_feat[M,Kn] = A[M,K] @ B[K,Kn] --------------------
#define BM 64
#define BN 64
#define BK 16

__global__ void sgemm_kernel(const float* __restrict__ Aext,
                             const float* __restrict__ B,
                             int M, int K, int Kn, int use_hbuf) {
    __shared__ float As[BK][BM + 1];
    __shared__ float Bs[BK][BN];
    const float* __restrict__ A = use_hbuf ? (const float*)g_hbuf : Aext;
    float* __restrict__ C = g_feat;

    int tid = threadIdx.x;
    int row0 = blockIdx.y * BM;
    int col0 = blockIdx.x * BN;
    int tx = tid & 15;
    int ty = tid >> 4;

    int a_m = tid >> 2;
    int a_k = (tid & 3) << 2;
    int b_k = tid >> 4;
    int b_n = (tid & 15) << 2;

    float acc[4][4];
#pragma unroll
    for (int i = 0; i < 4; i++)
#pragma unroll
        for (int j = 0; j < 4; j++) acc[i][j] = 0.f;

    for (int k0 = 0; k0 < K; k0 += BK) {
        float4 av = make_float4(0.f, 0.f, 0.f, 0.f);
        if (row0 + a_m < M)
            av = *(const float4*)(A + (size_t)(row0 + a_m) * K + k0 + a_k);
        As[a_k + 0][a_m] = av.x;
        As[a_k + 1][a_m] = av.y;
        As[a_k + 2][a_m] = av.z;
        As[a_k + 3][a_m] = av.w;

        float4 bv = make_float4(0.f, 0.f, 0.f, 0.f);
        int bc = col0 + b_n;
        if (bc < Kn)
            bv = *(const float4*)(B + (size_t)(k0 + b_k) * Kn + bc);
        *(float4*)&Bs[b_k][b_n] = bv;

        __syncthreads();

#pragma unroll
        for (int k = 0; k < BK; k++) {
            float ar[4], br[4];
#pragma unroll
            for (int i = 0; i < 4; i++) ar[i] = As[k][ty * 4 + i];
#pragma unroll
            for (int j = 0; j < 4; j++) br[j] = Bs[k][tx * 4 + j];
#pragma unroll
            for (int i = 0; i < 4; i++)
#pragma unroll
                for (int j = 0; j < 4; j++)
                    acc[i][j] = fmaf(ar[i], br[j], acc[i][j]);
        }
        __syncthreads();
    }

    int col = col0 + tx * 4;
#pragma unroll
    for (int i = 0; i < 4; i++) {
        int row = row0 + ty * 4 + i;
        if (row < M && col < Kn) {
            float4 v = make_float4(acc[i][0], acc[i][1], acc[i][2], acc[i][3]);
            *(float4*)(C + (size_t)row * Kn + col) = v;
        }
    }
}

// ---------------- per-node attention projections (el, er) -------------------
__global__ void elr_kernel(const float* __restrict__ al,
                           const float* __restrict__ ar,
                           int F) {
    int w = (blockIdx.x * blockDim.x + threadIdx.x) >> 5;
    int lane = threadIdx.x & 31;
    if (w >= NN) return;
    const float* frow = g_feat + (size_t)w * HH * F;
#pragma unroll
    for (int h = 0; h < HH; h++) {
        float sl = 0.f, sr = 0.f;
        for (int d = lane; d < F; d += 32) {
            float f = frow[h * F + d];
            sl = fmaf(f, al[h * F + d], sl);
            sr = fmaf(f, ar[h * F + d], sr);
        }
        sl = warpsum(sl);
        sr = warpsum(sr);
        if (lane == 0) {
            g_el[w * HH + h] = sl;
            g_er[w * HH + h] = sr;
        }
    }
}

// ---------------- fused softmax + aggregation, layers 1/2 (HF=128) ----------
// One warp per destination node. No atomics. Writes relu(acc + bias) to g_hbuf.
__global__ void aggr128_kernel(const float* __restrict__ bias) {
    int node = (blockIdx.x * blockDim.x + threadIdx.x) >> 5;
    int lane = threadIdx.x & 31;
    if (node >= NN) return;
    int beg = g_off[node], end = g_off[node + 1];
    float4 er4 = *(const float4*)(g_el + 0, g_er + (size_t)node * 4) ;
    er4 = *(const float4*)(g_er + (size_t)node * 4);

    // pass 1: segment max per head
    float m0 = -FLT_MAX, m1 = -FLT_MAX, m2 = -FLT_MAX, m3 = -FLT_MAX;
    for (int base = beg; base < end; base += 32) {
        int p = base + lane;
        if (p < end) {
            int s = g_esrc[p];
            float4 el4 = *(const float4*)(g_el + (size_t)s * 4);
            m0 = fmaxf(m0, lrelu(el4.x + er4.x));
            m1 = fmaxf(m1, lrelu(el4.y + er4.y));
            m2 = fmaxf(m2, lrelu(el4.z + er4.z));
            m3 = fmaxf(m3, lrelu(el4.w + er4.w));
        }
    }
    m0 = warpmax(m0); m1 = warpmax(m1); m2 = warpmax(m2); m3 = warpmax(m3);

    // pass 2: segment sum of exp
    float d0 = 0.f, d1 = 0.f, d2 = 0.f, d3 = 0.f;
    for (int base = beg; base < end; base += 32) {
        int p = base + lane;
        if (p < end) {
            int s = g_esrc[p];
            float4 el4 = *(const float4*)(g_el + (size_t)s * 4);
            d0 += __expf(lrelu(el4.x + er4.x) - m0);
            d1 += __expf(lrelu(el4.y + er4.y) - m1);
            d2 += __expf(lrelu(el4.z + er4.z) - m2);
            d3 += __expf(lrelu(el4.w + er4.w) - m3);
        }
    }
    d0 = warpsum(d0); d1 = warpsum(d1); d2 = warpsum(d2); d3 = warpsum(d3);
    float i0 = 1.f / d0, i1 = 1.f / d1, i2 = 1.f / d2, i3 = 1.f / d3;

    // pass 3: alpha-weighted gather-accumulate (lane = feature dim)
    float a0 = 0.f, a1 = 0.f, a2 = 0.f, a3 = 0.f;
    for (int base = beg; base < end; base += 32) {
        int p = base + lane;
        int cnt = min(32, end - base);
        int s = 0;
        float x0 = 0.f, x1 = 0.f, x2 = 0.f, x3 = 0.f;
        if (p < end) {
            s = g_esrc[p];
            float4 el4 = *(const float4*)(g_el + (size_t)s * 4);
            x0 = __expf(lrelu(el4.x + er4.x) - m0) * i0;
            x1 = __expf(lrelu(el4.y + er4.y) - m1) * i1;
            x2 = __expf(lrelu(el4.z + er4.z) - m2) * i2;
            x3 = __expf(lrelu(el4.w + er4.w) - m3) * i3;
        }
        for (int j = 0; j < cnt; j++) {
            int sj = __shfl_sync(FULLMASK, s, j);
            float w0 = __shfl_sync(FULLMASK, x0, j);
            float w1 = __shfl_sync(FULLMASK, x1, j);
            float w2 = __shfl_sync(FULLMASK, x2, j);
            float w3 = __shfl_sync(FULLMASK, x3, j);
            const float* fr = g_feat + (size_t)sj * HD;
            a0 = fmaf(w0, fr[lane], a0);
            a1 = fmaf(w1, fr[32 + lane], a1);
            a2 = fmaf(w2, fr[64 + lane], a2);
            a3 = fmaf(w3, fr[96 + lane], a3);
        }
    }
    float* hr = g_hbuf + (size_t)node * HD;
    hr[lane]      = fmaxf(a0 + bias[lane],      0.f);
    hr[32 + lane] = fmaxf(a1 + bias[32 + lane], 0.f);
    hr[64 + lane] = fmaxf(a2 + bias[64 + lane], 0.f);
    hr[96 + lane] = fmaxf(a3 + bias[96 + lane], 0.f);
}

// ---------------- fused softmax + aggr + head-mean + log_softmax, layer 3 ---
// One warp per destination node; accumulates head-SUM of alpha_h * feat.
__global__ void aggr47_final_kernel(const float* __restrict__ b3,
                                    float* __restrict__ out) {
    int node = (blockIdx.x * blockDim.x + threadIdx.x) >> 5;
    int lane = threadIdx.x & 31;
    if (node >= NN) return;
    int beg = g_off[node], end = g_off[node + 1];
    float4 er4 = *(const float4*)(g_er + (size_t)node * 4);

    float m0 = -FLT_MAX, m1 = -FLT_MAX, m2 = -FLT_MAX, m3 = -FLT_MAX;
    for (int base = beg; base < end; base += 32) {
        int p = base + lane;
        if (p < end) {
            int s = g_esrc[p];
            float4 el4 = *(const float4*)(g_el + (size_t)s * 4);
            m0 = fmaxf(m0, lrelu(el4.x + er4.x));
            m1 = fmaxf(m1, lrelu(el4.y + er4.y));
            m2 = fmaxf(m2, lrelu(el4.z + er4.z));
            m3 = fmaxf(m3, lrelu(el4.w + er4.w));
        }
    }
    m0 = warpmax(m0); m1 = warpmax(m1); m2 = warpmax(m2); m3 = warpmax(m3);

    float d0 = 0.f, d1 = 0.f, d2 = 0.f, d3 = 0.f;
    for (int base = beg; base < end; base += 32) {
        int p = base + lane;
        if (p < end) {
            int s = g_esrc[p];
            float4 el4 = *(const float4*)(g_el + (size_t)s * 4);
            d0 += __expf(lrelu(el4.x + er4.x) - m0);
            d1 += __expf(lrelu(el4.y + er4.y) - m1);
            d2 += __expf(lrelu(el4.z + er4.z) - m2);
            d3 += __expf(lrelu(el4.w + er4.w) - m3);
        }
    }
    d0 = warpsum(d0); d1 = warpsum(d1); d2 = warpsum(d2); d3 = warpsum(d3);
    float i0 = 1.f / d0, i1 = 1.f / d1, i2 = 1.f / d2, i3 = 1.f / d3;

    // head-sum accumulation: lane covers classes c0 = lane, c1 = lane + 32
    float a0 = 0.f, a1 = 0.f;
    for (int base = beg; base < end; base += 32) {
        int p = base + lane;
        int cnt = min(32, end - base);
        int s = 0;
        float x0 = 0.f, x1 = 0.f, x2 = 0.f, x3 = 0.f;
        if (p < end) {
            s = g_esrc[p];
            float4 el4 = *(const float4*)(g_el + (size_t)s * 4);
            x0 = __expf(lrelu(el4.x + er4.x) - m0) * i0;
            x1 = __expf(lrelu(el4.y + er4.y) - m1) * i1;
            x2 = __expf(lrelu(el4.z + er4.z) - m2) * i2;
            x3 = __expf(lrelu(el4.w + er4.w) - m3) * i3;
        }
        for (int j = 0; j < cnt; j++) {
            int sj = __shfl_sync(FULLMASK, s, j);
            float w0 = __shfl_sync(FULLMASK, x0, j);
            float w1 = __shfl_sync(FULLMASK, x1, j);
            float w2 = __shfl_sync(FULLMASK, x2, j);
            float w3 = __shfl_sync(FULLMASK, x3, j);
            const float* fr = g_feat + (size_t)sj * HC;
            a0 += w0 * fr[lane] + w1 * fr[CC + lane]
                + w2 * fr[2 * CC + lane] + w3 * fr[3 * CC + lane];
            if (lane < CC - 32) {
                int c = 32 + lane;
                a1 += w0 * fr[c] + w1 * fr[CC + c]
                    + w2 * fr[2 * CC + c] + w3 * fr[3 * CC + c];
            }
        }
    }
    // bias (head mean) + mean over heads
    float v0 = a0 * 0.25f + 0.25f * (b3[lane] + b3[CC + lane] +
                                     b3[2 * CC + lane] + b3[3 * CC + lane]);
    float v1 = 0.f;
    if (lane < CC - 32) {
        int c = 32 + lane;
        v1 = a1 * 0.25f + 0.25f * (b3[c] + b3[CC + c] +
                                   b3[2 * CC + c] + b3[3 * CC + c]);
    }
    // warp log_softmax over 47 classes
    float mm = v0;
    if (lane < CC - 32) mm = fmaxf(mm, v1);
    mm = warpmax(mm);
    float s = __expf(v0 - mm);
    if (lane < CC - 32) s += __expf(v1 - mm);
    s = warpsum(s);
    float lse = logf(s) + mm;
    out[(size_t)node * CC + lane] = v0 - lse;
    if (lane < CC - 32) out[(size_t)node * CC + 32 + lane] = v1 - lse;
}

// ---------------- host orchestration ----------------------------------------
extern "C" void kernel_launch(void* const* d_in, const int* in_sizes, int n_in,
                              void* d_out, int out_size) {
    const float* x   = (const float*)d_in[0];
    const int*   src = (const int*)  d_in[1];
    const int*   dst = (const int*)  d_in[2];
    const float* W1  = (const float*)d_in[3];
    const float* al1 = (const float*)d_in[4];
    const float* ar1 = (const float*)d_in[5];
    const float* b1  = (const float*)d_in[6];
    const float* W2  = (const float*)d_in[7];
    const float* al2 = (const float*)d_in[8];
    const float* ar2 = (const float*)d_in[9];
    const float* b2  = (const float*)d_in[10];
    const float* W3  = (const float*)d_in[11];
    const float* al3 = (const float*)d_in[12];
    const float* ar3 = (const float*)d_in[13];
    const float* b3  = (const float*)d_in[14];
    float* out = (float*)d_out;

    // ---- CSR build (once; same graph for all 3 layers) ----
    zero_deg_kernel<<<(NN + 255) / 256, 256>>>();
    hist_kernel<<<(EE + 255) / 256, 256>>>(dst);
    scan_kernel<<<1, 1024>>>();
    scatter_kernel<<<(EE + 255) / 256, 256>>>(src, dst);

    int node_warp_blocks = (NN * 32 + 255) / 256;

    // ---- Layer 1: IN -> H*D, ReLU ----
    {
        dim3 ggrid((HD + BN - 1) / BN, (NN + BM - 1) / BM);
        sgemm_kernel<<<ggrid, 256>>>(x, W1, NN, IN_F, HD, 0);
        elr_kernel<<<node_warp_blocks, 256>>>(al1, ar1, DD);
        aggr128_kernel<<<node_warp_blocks, 256>>>(b1);
    }
    // ---- Layer 2: H*D -> H*D, ReLU ----
    {
        dim3 ggrid((HD + BN - 1) / BN, (NN + BM - 1) / BM);
        sgemm_kernel<<<ggrid, 256>>>(nullptr, W2, NN, HD, HD, 1);
        elr_kernel<<<node_warp_blocks, 256>>>(al2, ar2, DD);
        aggr128_kernel<<<node_warp_blocks, 256>>>(b2);
    }
    // ---- Layer 3: H*D -> H*C, head-mean + log_softmax ----
    {
        dim3 ggrid((HC + BN - 1) / BN, (NN + BM - 1) / BM);
        sgemm_kernel<<<ggrid, 256>>>(nullptr, W3, NN, HD, HC, 1);
        elr_kernel<<<node_warp_blocks, 256>>>(al3, ar3, CC);
        aggr47_final_kernel<<<node_warp_blocks, 256>>>(b3, out);
    }
}

// round 6
// speedup vs baseline: 2.6829x; 1.0953x over previous
#include <cuda_runtime.h>
#include <math.h>
#include <float.h>

#define NN 100000
#define EE 1600000
#define IN_F 256
#define HH 4
#define DD 32
#define CC 47
#define HD 128        // H*D
#define HC 188        // H*C
#define NEG_SLOPE 0.2f
#define FULLMASK 0xffffffffu

// ---------------- scratch (static device globals; no allocation) ------------
__device__ __align__(16) float g_feat[(size_t)NN * HC];
__device__ __align__(16) float g_hbuf[(size_t)NN * HD];
__device__ __align__(16) float g_el[NN * HH];
__device__ __align__(16) float g_er[NN * HH];
__device__ int g_deg[NN];
__device__ int g_off[NN + 1];
__device__ int g_cur[NN];
__device__ int g_esrc[EE];

// ---------------- warp helpers ----------------------------------------------
__device__ __forceinline__ float warpsum(float v) {
#pragma unroll
    for (int o = 16; o; o >>= 1) v += __shfl_xor_sync(FULLMASK, v, o);
    return v;
}
__device__ __forceinline__ float warpmax(float v) {
#pragma unroll
    for (int o = 16; o; o >>= 1) v = fmaxf(v, __shfl_xor_sync(FULLMASK, v, o));
    return v;
}
__device__ __forceinline__ float lrelu(float v) {
    return v > 0.f ? v : NEG_SLOPE * v;
}

// ---------------- CSR build --------------------------------------------------
__global__ void zero_deg_kernel() {
    int i = blockIdx.x * blockDim.x + threadIdx.x;
    if (i < NN) g_deg[i] = 0;
}
__global__ void hist_kernel(const int* __restrict__ dst) {
    int e = blockIdx.x * blockDim.x + threadIdx.x;
    if (e < EE) atomicAdd(&g_deg[dst[e]], 1);
}
// single block, 1024 threads, warp-shuffle based scan (3 barriers per tile)
__global__ void scan_kernel() {
    __shared__ int warpsums[32];
    __shared__ int s_carry;
    int tid = threadIdx.x;
    int lane = tid & 31, wid = tid >> 5;
    if (tid == 0) s_carry = 0;
    __syncthreads();
    for (int base = 0; base < NN; base += 1024) {
        int i = base + tid;
        int v = (i < NN) ? g_deg[i] : 0;
        int x = v;
#pragma unroll
        for (int o = 1; o < 32; o <<= 1) {
            int t = __shfl_up_sync(FULLMASK, x, o);
            if (lane >= o) x += t;
        }
        if (lane == 31) warpsums[wid] = x;
        __syncthreads();
        if (wid == 0) {
            int w = warpsums[lane];
#pragma unroll
            for (int o = 1; o < 32; o <<= 1) {
                int t = __shfl_up_sync(FULLMASK, w, o);
                if (lane >= o) w += t;
            }
            warpsums[lane] = w;
        }
        __syncthreads();
        int warpoff = (wid == 0) ? 0 : warpsums[wid - 1];
        int incl = x + warpoff;
        int excl = incl - v;
        int carry = s_carry;
        if (i < NN) { g_off[i] = carry + excl; g_cur[i] = carry + excl; }
        __syncthreads();
        if (tid == 1023) s_carry = carry + incl;
        __syncthreads();
    }
    if (tid == 0) g_off[NN] = s_carry;
}
__global__ void scatter_kernel(const int* __restrict__ src,
                               const int* __restrict__ dst) {
    int e = blockIdx.x * blockDim.x + threadIdx.x;
    if (e >= EE) return;
    int p = atomicAdd(&g_cur[dst[e]], 1);
    g_esrc[p] = src[e];
}

// ---------------- SGEMM v2: g_feat[M,Kn] = A[M,K] @ B[K,Kn] -----------------
// BM=128, BK=16, templated BN (128 or 64), 256 threads, 8 x TN microtile,
// vectorized smem, register-staged global prefetch.
template<int TBN, int TTN>
__global__ void __launch_bounds__(256, 2)
sgemm_kernel(const float* __restrict__ Aext,
             const float* __restrict__ B,
             int M, int K, int Kn, int use_hbuf) {
    constexpr int TBM = 128;
    constexpr int TBK = 16;
    constexpr int NB = TBN / 64;            // B float4 loads per thread (1 or 2)
    constexpr int BROWSTEP = TBK / NB;      // row stride between B loads
    __shared__ float As[TBK][TBM];          // transposed A tile
    __shared__ float Bs[TBK][TBN];

    const float* __restrict__ A = use_hbuf ? (const float*)g_hbuf : Aext;

    int tid = threadIdx.x;
    int row0 = blockIdx.y * TBM;
    int col0 = blockIdx.x * TBN;
    int tx = tid & 15;                      // 0..15 -> cols tx*TTN
    int ty = tid >> 4;                      // 0..15 -> rows ty*8

    // A staging: row a_m, k-offsets a_k .. a_k+7 (2 float4)
    int a_m = tid >> 1;
    int a_k = (tid & 1) * 8;
    // B staging: NB float4
    int b_k = tid / (TBN / 4);
    int b_n = (tid % (TBN / 4)) * 4;

    float4 aS[2], bS[NB];

    auto loadG = [&](int k0) {
        int row = row0 + a_m;
        if (row < M) {
            const float* ap = A + (size_t)row * K + k0 + a_k;
            aS[0] = *(const float4*)(ap);
            aS[1] = *(const float4*)(ap + 4);
        } else {
            aS[0] = make_float4(0.f, 0.f, 0.f, 0.f);
            aS[1] = aS[0];
        }
        int col = col0 + b_n;
#pragma unroll
        for (int r = 0; r < NB; r++) {
            if (col < Kn)
                bS[r] = *(const float4*)(B + (size_t)(k0 + b_k + r * BROWSTEP) * Kn + col);
            else
                bS[r] = make_float4(0.f, 0.f, 0.f, 0.f);
        }
    };
    auto storeS = [&]() {
        As[a_k + 0][a_m] = aS[0].x;
        As[a_k + 1][a_m] = aS[0].y;
        As[a_k + 2][a_m] = aS[0].z;
        As[a_k + 3][a_m] = aS[0].w;
        As[a_k + 4][a_m] = aS[1].x;
        As[a_k + 5][a_m] = aS[1].y;
        As[a_k + 6][a_m] = aS[1].z;
        As[a_k + 7][a_m] = aS[1].w;
#pragma unroll
        for (int r = 0; r < NB; r++)
            *(float4*)&Bs[b_k + r * BROWSTEP][b_n] = bS[r];
    };

    float acc[8][TTN];
#pragma unroll
    for (int i = 0; i < 8; i++)
#pragma unroll
        for (int j = 0; j < TTN; j++) acc[i][j] = 0.f;

    loadG(0);
    storeS();
    __syncthreads();

    for (int k0 = 0; k0 < K; k0 += TBK) {
        bool more = (k0 + TBK < K);
        if (more) loadG(k0 + TBK);
#pragma unroll
        for (int k = 0; k < TBK; k++) {
            float ar[8], br[TTN];
            float4 t0 = *(const float4*)&As[k][ty * 8];
            float4 t1 = *(const float4*)&As[k][ty * 8 + 4];
            ar[0] = t0.x; ar[1] = t0.y; ar[2] = t0.z; ar[3] = t0.w;
            ar[4] = t1.x; ar[5] = t1.y; ar[6] = t1.z; ar[7] = t1.w;
#pragma unroll
            for (int j4 = 0; j4 < TTN / 4; j4++) {
                float4 tb = *(const float4*)&Bs[k][tx * TTN + j4 * 4];
                br[j4 * 4 + 0] = tb.x; br[j4 * 4 + 1] = tb.y;
                br[j4 * 4 + 2] = tb.z; br[j4 * 4 + 3] = tb.w;
            }
#pragma unroll
            for (int i = 0; i < 8; i++)
#pragma unroll
                for (int j = 0; j < TTN; j++)
                    acc[i][j] = fmaf(ar[i], br[j], acc[i][j]);
        }
        if (more) {
            __syncthreads();
            storeS();
            __syncthreads();
        }
    }

#pragma unroll
    for (int i = 0; i < 8; i++) {
        int row = row0 + ty * 8 + i;
        if (row < M) {
#pragma unroll
            for (int j4 = 0; j4 < TTN / 4; j4++) {
                int col = col0 + tx * TTN + j4 * 4;
                if (col < Kn) {
                    float4 v = make_float4(acc[i][j4 * 4 + 0], acc[i][j4 * 4 + 1],
                                           acc[i][j4 * 4 + 2], acc[i][j4 * 4 + 3]);
                    *(float4*)(g_feat + (size_t)row * Kn + col) = v;
                }
            }
        }
    }
}

// ---------------- per-node attention projections (el, er) -------------------
__global__ void elr_kernel(const float* __restrict__ al,
                           const float* __restrict__ ar,
                           int F) {
    int w = (blockIdx.x * blockDim.x + threadIdx.x) >> 5;
    int lane = threadIdx.x & 31;
    if (w >= NN) return;
    const float* frow = g_feat + (size_t)w * HH * F;
#pragma unroll
    for (int h = 0; h < HH; h++) {
        float sl = 0.f, sr = 0.f;
        for (int d = lane; d < F; d += 32) {
            float f = frow[h * F + d];
            sl = fmaf(f, al[h * F + d], sl);
            sr = fmaf(f, ar[h * F + d], sr);
        }
        sl = warpsum(sl);
        sr = warpsum(sr);
        if (lane == 0) {
            g_el[w * HH + h] = sl;
            g_er[w * HH + h] = sr;
        }
    }
}

// ---------------- fused softmax + aggregation, layers 1/2 (HF=128) ----------
// One warp per dst node. No max-pass (logits are small; exp is safe and the
// result is mathematically identical). Per-edge exps cached in registers for
// deg <= 128 (covers ~all nodes at mean degree 16); recompute tail beyond.
#define NCH 4
__global__ void aggr128_kernel(const float* __restrict__ bias) {
    int node = (blockIdx.x * blockDim.x + threadIdx.x) >> 5;
    int lane = threadIdx.x & 31;
    if (node >= NN) return;
    int beg = g_off[node], end = g_off[node + 1];
    int deg = end - beg;
    float4 er4 = *(const float4*)(g_er + (size_t)node * 4);

    int   sc[NCH];
    float x0c[NCH], x1c[NCH], x2c[NCH], x3c[NCH];
    float d0 = 0.f, d1 = 0.f, d2 = 0.f, d3 = 0.f;
    int nch = (deg + 31) >> 5; if (nch > NCH) nch = NCH;

#pragma unroll
    for (int c = 0; c < NCH; c++) {
        sc[c] = 0; x0c[c] = 0.f; x1c[c] = 0.f; x2c[c] = 0.f; x3c[c] = 0.f;
        if (c < nch) {
            int p = beg + c * 32 + lane;
            if (p < end) {
                int s = g_esrc[p]; sc[c] = s;
                float4 el4 = *(const float4*)(g_el + (size_t)s * 4);
                float e0 = __expf(lrelu(el4.x + er4.x));
                float e1 = __expf(lrelu(el4.y + er4.y));
                float e2 = __expf(lrelu(el4.z + er4.z));
                float e3 = __expf(lrelu(el4.w + er4.w));
                x0c[c] = e0; x1c[c] = e1; x2c[c] = e2; x3c[c] = e3;
                d0 += e0; d1 += e1; d2 += e2; d3 += e3;
            }
        }
    }
    // tail: denominator only (deg > 128, rare)
    for (int p = beg + NCH * 32 + lane; p < end; p += 32) {
        int s = g_esrc[p];
        float4 el4 = *(const float4*)(g_el + (size_t)s * 4);
        d0 += __expf(lrelu(el4.x + er4.x));
        d1 += __expf(lrelu(el4.y + er4.y));
        d2 += __expf(lrelu(el4.z + er4.z));
        d3 += __expf(lrelu(el4.w + er4.w));
    }
    d0 = warpsum(d0); d1 = warpsum(d1); d2 = warpsum(d2); d3 = warpsum(d3);
    float i0 = 1.f / d0, i1 = 1.f / d1, i2 = 1.f / d2, i3 = 1.f / d3;
#pragma unroll
    for (int c = 0; c < NCH; c++) {
        x0c[c] *= i0; x1c[c] *= i1; x2c[c] *= i2; x3c[c] *= i3;
    }

    int h = lane >> 3;                       // head of this lane's 4 dims
    float4 acc = make_float4(0.f, 0.f, 0.f, 0.f);
#pragma unroll
    for (int c = 0; c < NCH; c++) {
        if (c < nch) {
            int cnt = min(32, deg - c * 32);
            for (int j = 0; j < cnt; j++) {
                int sj = __shfl_sync(FULLMASK, sc[c], j);
                float w0 = __shfl_sync(FULLMASK, x0c[c], j);
                float w1 = __shfl_sync(FULLMASK, x1c[c], j);
                float w2 = __shfl_sync(FULLMASK, x2c[c], j);
                float w3 = __shfl_sync(FULLMASK, x3c[c], j);
                float w = h == 0 ? w0 : (h == 1 ? w1 : (h == 2 ? w2 : w3));
                float4 f = *(const float4*)(g_feat + (size_t)sj * HD + lane * 4);
                acc.x = fmaf(w, f.x, acc.x);
                acc.y = fmaf(w, f.y, acc.y);
                acc.z = fmaf(w, f.z, acc.z);
                acc.w = fmaf(w, f.w, acc.w);
            }
        }
    }
    // tail: recompute alphas (deg > 128, rare)
    for (int base = beg + NCH * 32; base < end; base += 32) {
        int p = base + lane;
        int cnt = min(32, end - base);
        int s = 0; float x0 = 0.f, x1 = 0.f, x2 = 0.f, x3 = 0.f;
        if (p < end) {
            s = g_esrc[p];
            float4 el4 = *(const float4*)(g_el + (size_t)s * 4);
            x0 = __expf(lrelu(el4.x + er4.x)) * i0;
            x1 = __expf(lrelu(el4.y + er4.y)) * i1;
            x2 = __expf(lrelu(el4.z + er4.z)) * i2;
            x3 = __expf(lrelu(el4.w + er4.w)) * i3;
        }
        for (int j = 0; j < cnt; j++) {
            int sj = __shfl_sync(FULLMASK, s, j);
            float w0 = __shfl_sync(FULLMASK, x0, j);
            float w1 = __shfl_sync(FULLMASK, x1, j);
            float w2 = __shfl_sync(FULLMASK, x2, j);
            float w3 = __shfl_sync(FULLMASK, x3, j);
            float w = h == 0 ? w0 : (h == 1 ? w1 : (h == 2 ? w2 : w3));
            float4 f = *(const float4*)(g_feat + (size_t)sj * HD + lane * 4);
            acc.x = fmaf(w, f.x, acc.x);
            acc.y = fmaf(w, f.y, acc.y);
            acc.z = fmaf(w, f.z, acc.z);
            acc.w = fmaf(w, f.w, acc.w);
        }
    }

    float4 bv = *(const float4*)(bias + lane * 4);
    float4 o;
    o.x = fmaxf(acc.x + bv.x, 0.f);
    o.y = fmaxf(acc.y + bv.y, 0.f);
    o.z = fmaxf(acc.z + bv.z, 0.f);
    o.w = fmaxf(acc.w + bv.w, 0.f);
    *(float4*)(g_hbuf + (size_t)node * HD + lane * 4) = o;
}

// ---------------- fused softmax + aggr + head-mean + log_softmax, layer 3 ---
__global__ void aggr47_final_kernel(const float* __restrict__ b3,
                                    float* __restrict__ out) {
    int node = (blockIdx.x * blockDim.x + threadIdx.x) >> 5;
    int lane = threadIdx.x & 31;
    if (node >= NN) return;
    int beg = g_off[node], end = g_off[node + 1];
    int deg = end - beg;
    float4 er4 = *(const float4*)(g_er + (size_t)node * 4);

    int   sc[NCH];
    float x0c[NCH], x1c[NCH], x2c[NCH], x3c[NCH];
    float d0 = 0.f, d1 = 0.f, d2 = 0.f, d3 = 0.f;
    int nch = (deg + 31) >> 5; if (nch > NCH) nch = NCH;

#pragma unroll
    for (int c = 0; c < NCH; c++) {
        sc[c] = 0; x0c[c] = 0.f; x1c[c] = 0.f; x2c[c] = 0.f; x3c[c] = 0.f;
        if (c < nch) {
            int p = beg + c * 32 + lane;
            if (p < end) {
                int s = g_esrc[p]; sc[c] = s;
                float4 el4 = *(const float4*)(g_el + (size_t)s * 4);
                float e0 = __expf(lrelu(el4.x + er4.x));
                float e1 = __expf(lrelu(el4.y + er4.y));
                float e2 = __expf(lrelu(el4.z + er4.z));
                float e3 = __expf(lrelu(el4.w + er4.w));
                x0c[c] = e0; x1c[c] = e1; x2c[c] = e2; x3c[c] = e3;
                d0 += e0; d1 += e1; d2 += e2; d3 += e3;
            }
        }
    }
    for (int p = beg + NCH * 32 + lane; p < end; p += 32) {
        int s = g_esrc[p];
        float4 el4 = *(const float4*)(g_el + (size_t)s * 4);
        d0 += __expf(lrelu(el4.x + er4.x));
        d1 += __expf(lrelu(el4.y + er4.y));
        d2 += __expf(lrelu(el4.z + er4.z));
        d3 += __expf(lrelu(el4.w + er4.w));
    }
    d0 = warpsum(d0); d1 = warpsum(d1); d2 = warpsum(d2); d3 = warpsum(d3);
    float i0 = 1.f / d0, i1 = 1.f / d1, i2 = 1.f / d2, i3 = 1.f / d3;
#pragma unroll
    for (int c = 0; c < NCH; c++) {
        x0c[c] *= i0; x1c[c] *= i1; x2c[c] *= i2; x3c[c] *= i3;
    }

    // head-sum accumulation: lane covers classes lane and lane+32
    float a0 = 0.f, a1 = 0.f;
#pragma unroll
    for (int c = 0; c < NCH; c++) {
        if (c < nch) {
            int cnt = min(32, deg - c * 32);
            for (int j = 0; j < cnt; j++) {
                int sj = __shfl_sync(FULLMASK, sc[c], j);
                float w0 = __shfl_sync(FULLMASK, x0c[c], j);
                float w1 = __shfl_sync(FULLMASK, x1c[c], j);
                float w2 = __shfl_sync(FULLMASK, x2c[c], j);
                float w3 = __shfl_sync(FULLMASK, x3c[c], j);
                const float* fr = g_feat + (size_t)sj * HC;
                a0 += w0 * fr[lane] + w1 * fr[CC + lane]
                    + w2 * fr[2 * CC + lane] + w3 * fr[3 * CC + lane];
                if (lane < CC - 32) {
                    int cx = 32 + lane;
                    a1 += w0 * fr[cx] + w1 * fr[CC + cx]
                        + w2 * fr[2 * CC + cx] + w3 * fr[3 * CC + cx];
                }
            }
        }
    }
    for (int base = beg + NCH * 32; base < end; base += 32) {
        int p = base + lane;
        int cnt = min(32, end - base);
        int s = 0; float x0 = 0.f, x1 = 0.f, x2 = 0.f, x3 = 0.f;
        if (p < end) {
            s = g_esrc[p];
            float4 el4 = *(const float4*)(g_el + (size_t)s * 4);
            x0 = __expf(lrelu(el4.x + er4.x)) * i0;
            x1 = __expf(lrelu(el4.y + er4.y)) * i1;
            x2 = __expf(lrelu(el4.z + er4.z)) * i2;
            x3 = __expf(lrelu(el4.w + er4.w)) * i3;
        }
        for (int j = 0; j < cnt; j++) {
            int sj = __shfl_sync(FULLMASK, s, j);
            float w0 = __shfl_sync(FULLMASK, x0, j);
            float w1 = __shfl_sync(FULLMASK, x1, j);
            float w2 = __shfl_sync(FULLMASK, x2, j);
            float w3 = __shfl_sync(FULLMASK, x3, j);
            const float* fr = g_feat + (size_t)sj * HC;
            a0 += w0 * fr[lane] + w1 * fr[CC + lane]
                + w2 * fr[2 * CC + lane] + w3 * fr[3 * CC + lane];
            if (lane < CC - 32) {
                int cx = 32 + lane;
                a1 += w0 * fr[cx] + w1 * fr[CC + cx]
                    + w2 * fr[2 * CC + cx] + w3 * fr[3 * CC + cx];
            }
        }
    }

    float v0 = a0 * 0.25f + 0.25f * (b3[lane] + b3[CC + lane] +
                                     b3[2 * CC + lane] + b3[3 * CC + lane]);
    float v1 = 0.f;
    if (lane < CC - 32) {
        int cx = 32 + lane;
        v1 = a1 * 0.25f + 0.25f * (b3[cx] + b3[CC + cx] +
                                   b3[2 * CC + cx] + b3[3 * CC + cx]);
    }
    float mm = v0;
    if (lane < CC - 32) mm = fmaxf(mm, v1);
    mm = warpmax(mm);
    float s = __expf(v0 - mm);
    if (lane < CC - 32) s += __expf(v1 - mm);
    s = warpsum(s);
    float lse = logf(s) + mm;
    out[(size_t)node * CC + lane] = v0 - lse;
    if (lane < CC - 32) out[(size_t)node * CC + 32 + lane] = v1 - lse;
}

// ---------------- host orchestration ----------------------------------------
extern "C" void kernel_launch(void* const* d_in, const int* in_sizes, int n_in,
                              void* d_out, int out_size) {
    const float* x   = (const float*)d_in[0];
    const int*   src = (const int*)  d_in[1];
    const int*   dst = (const int*)  d_in[2];
    const float* W1  = (const float*)d_in[3];
    const float* al1 = (const float*)d_in[4];
    const float* ar1 = (const float*)d_in[5];
    const float* b1  = (const float*)d_in[6];
    const float* W2  = (const float*)d_in[7];
    const float* al2 = (const float*)d_in[8];
    const float* ar2 = (const float*)d_in[9];
    const float* b2  = (const float*)d_in[10];
    const float* W3  = (const float*)d_in[11];
    const float* al3 = (const float*)d_in[12];
    const float* ar3 = (const float*)d_in[13];
    const float* b3  = (const float*)d_in[14];
    float* out = (float*)d_out;

    // ---- CSR build (same graph for all 3 layers) ----
    zero_deg_kernel<<<(NN + 255) / 256, 256>>>();
    hist_kernel<<<(EE + 255) / 256, 256>>>(dst);
    scan_kernel<<<1, 1024>>>();
    scatter_kernel<<<(EE + 255) / 256, 256>>>(src, dst);

    int node_warp_blocks = (NN * 32 + 255) / 256;
    int mblocks = (NN + 127) / 128;

    // ---- Layer 1: IN -> H*D, ReLU ----
    sgemm_kernel<128, 8><<<dim3(1, mblocks), 256>>>(x, W1, NN, IN_F, HD, 0);
    elr_kernel<<<node_warp_blocks, 256>>>(al1, ar1, DD);
    aggr128_kernel<<<node_warp_blocks, 256>>>(b1);

    // ---- Layer 2: H*D -> H*D, ReLU ----
    sgemm_kernel<128, 8><<<dim3(1, mblocks), 256>>>(nullptr, W2, NN, HD, HD, 1);
    elr_kernel<<<node_warp_blocks, 256>>>(al2, ar2, DD);
    aggr128_kernel<<<node_warp_blocks, 256>>>(b2);

    // ---- Layer 3: H*D -> H*C, head-mean + log_softmax ----
    sgemm_kernel<64, 4><<<dim3(3, mblocks), 256>>>(nullptr, W3, NN, HD, HC, 1);
    elr_kernel<<<node_warp_blocks, 256>>>(al3, ar3, CC);
    aggr47_final_kernel<<<node_warp_blocks, 256>>>(b3, out);
}

// round 7
// speedup vs baseline: 2.7346x; 1.0193x over previous
#include <cuda_runtime.h>
#include <math.h>
#include <float.h>

#define NN 100000
#define EE 1600000
#define IN_F 256
#define HH 4
#define DD 32
#define CC 47
#define HD 128        // H*D
#define HC 188        // H*C
#define NEG_SLOPE 0.2f
#define FULLMASK 0xffffffffu

// ---------------- scratch (static device globals; no allocation) ------------
__device__ __align__(16) float g_feat[(size_t)NN * HC];
__device__ __align__(16) float g_hbuf[(size_t)NN * HD];
__device__ __align__(16) float g_el[NN * HH];
__device__ __align__(16) float g_er[NN * HH];
__device__ int g_deg[NN];
__device__ int g_off[NN + 1];
__device__ int g_cur[NN];
__device__ int g_esrc[EE];

// ---------------- warp helpers ----------------------------------------------
__device__ __forceinline__ float warpsum(float v) {
#pragma unroll
    for (int o = 16; o; o >>= 1) v += __shfl_xor_sync(FULLMASK, v, o);
    return v;
}
__device__ __forceinline__ float warpmax(float v) {
#pragma unroll
    for (int o = 16; o; o >>= 1) v = fmaxf(v, __shfl_xor_sync(FULLMASK, v, o));
    return v;
}
__device__ __forceinline__ float lrelu(float v) {
    return v > 0.f ? v : NEG_SLOPE * v;
}
__device__ __forceinline__ unsigned f2tf(float x) {
    unsigned r;
    asm("cvt.rna.tf32.f32 %0, %1;" : "=r"(r) : "f"(x));
    return r;
}

// ---------------- CSR build --------------------------------------------------
__global__ void zero_deg_kernel() {
    int i = blockIdx.x * blockDim.x + threadIdx.x;
    if (i < NN) g_deg[i] = 0;
}
__global__ void hist_kernel(const int* __restrict__ dst) {
    int e = blockIdx.x * blockDim.x + threadIdx.x;
    if (e < EE) atomicAdd(&g_deg[dst[e]], 1);
}
__global__ void scan_kernel() {
    __shared__ int warpsums[32];
    __shared__ int s_carry;
    int tid = threadIdx.x;
    int lane = tid & 31, wid = tid >> 5;
    if (tid == 0) s_carry = 0;
    __syncthreads();
    for (int base = 0; base < NN; base += 1024) {
        int i = base + tid;
        int v = (i < NN) ? g_deg[i] : 0;
        int x = v;
#pragma unroll
        for (int o = 1; o < 32; o <<= 1) {
            int t = __shfl_up_sync(FULLMASK, x, o);
            if (lane >= o) x += t;
        }
        if (lane == 31) warpsums[wid] = x;
        __syncthreads();
        if (wid == 0) {
            int w = warpsums[lane];
#pragma unroll
            for (int o = 1; o < 32; o <<= 1) {
                int t = __shfl_up_sync(FULLMASK, w, o);
                if (lane >= o) w += t;
            }
            warpsums[lane] = w;
        }
        __syncthreads();
        int warpoff = (wid == 0) ? 0 : warpsums[wid - 1];
        int incl = x + warpoff;
        int excl = incl - v;
        int carry = s_carry;
        if (i < NN) { g_off[i] = carry + excl; g_cur[i] = carry + excl; }
        __syncthreads();
        if (tid == 1023) s_carry = carry + incl;
        __syncthreads();
    }
    if (tid == 0) g_off[NN] = s_carry;
}
__global__ void scatter_kernel(const int* __restrict__ src,
                               const int* __restrict__ dst) {
    int e = blockIdx.x * blockDim.x + threadIdx.x;
    if (e >= EE) return;
    int p = atomicAdd(&g_cur[dst[e]], 1);
    g_esrc[p] = src[e];
}

// ---------------- 3xTF32 tensor-core GEMM -----------------------------------
// g_feat[M,Kn] = A[M,K] @ B[K,Kn], fp32-equivalent accuracy via hi/lo split.
// Block tile 128x64, BK=16; 8 warps in 4(M) x 2(N); warp tile 32x32 =
// 2 m16 x 4 n8 mma tiles. Per k8 step: 8 tiles x 3 mma (AhBh, AhBl, AlBh).
#define GBM 128
#define GBN 64
#define GBK 16
#define ASTR (GBM + 8)   // stride 136 -> 136 % 32 = 8 -> conflict-free frags
#define BSTR (GBN + 8)   // stride 72  -> 72 % 32 = 8  -> conflict-free frags

__device__ __forceinline__ void mma_tf32(float* c, const unsigned* a, const unsigned* b) {
    asm("mma.sync.aligned.m16n8k8.row.col.f32.tf32.tf32.f32 "
        "{%0,%1,%2,%3}, {%4,%5,%6,%7}, {%8,%9}, {%0,%1,%2,%3};"
        : "+f"(c[0]), "+f"(c[1]), "+f"(c[2]), "+f"(c[3])
        : "r"(a[0]), "r"(a[1]), "r"(a[2]), "r"(a[3]), "r"(b[0]), "r"(b[1]));
}

__global__ void __launch_bounds__(256, 2)
tf32_gemm_kernel(const float* __restrict__ Aext,
                 const float* __restrict__ B,
                 int M, int K, int Kn, int use_hbuf) {
    __shared__ unsigned Ah[GBK][ASTR], Al[GBK][ASTR];
    __shared__ unsigned Bh[GBK][BSTR], Bl[GBK][BSTR];

    const float* __restrict__ A = use_hbuf ? (const float*)g_hbuf : Aext;

    int tid = threadIdx.x;
    int wid = tid >> 5, lane = tid & 31;
    int row0 = blockIdx.y * GBM, col0 = blockIdx.x * GBN;
    int m0 = (wid >> 1) * 32;           // warp M origin within tile
    int n0 = (wid & 1) * 32;            // warp N origin within tile
    int gq = lane >> 2;                 // groupID 0..7
    int tg = lane & 3;                  // thread-in-group 0..3

    // staging maps
    int a_m = tid >> 1;                 // 0..127
    int a_k = (tid & 1) * 8;            // 0 or 8
    int b_k = tid >> 4;                 // 0..15
    int b_n = (tid & 15) * 4;           // 0..60

    float aS[8];
    float bS[4];

    auto loadG = [&](int k0) {
        int row = row0 + a_m;
        if (row < M) {
            const float* ap = A + (size_t)row * K + k0 + a_k;
            float4 v0 = *(const float4*)(ap);
            float4 v1 = *(const float4*)(ap + 4);
            aS[0] = v0.x; aS[1] = v0.y; aS[2] = v0.z; aS[3] = v0.w;
            aS[4] = v1.x; aS[5] = v1.y; aS[6] = v1.z; aS[7] = v1.w;
        } else {
#pragma unroll
            for (int j = 0; j < 8; j++) aS[j] = 0.f;
        }
        int col = col0 + b_n;
        const float* bp = B + (size_t)(k0 + b_k) * Kn;
        if (col + 3 < Kn) {
            float4 v = *(const float4*)(bp + col);
            bS[0] = v.x; bS[1] = v.y; bS[2] = v.z; bS[3] = v.w;
        } else {
#pragma unroll
            for (int j = 0; j < 4; j++) bS[j] = (col + j < Kn) ? bp[col + j] : 0.f;
        }
    };
    auto storeS = [&]() {
#pragma unroll
        for (int j = 0; j < 8; j++) {
            unsigned h = f2tf(aS[j]);
            Ah[a_k + j][a_m] = h;
            Al[a_k + j][a_m] = f2tf(aS[j] - __uint_as_float(h));
        }
#pragma unroll
        for (int j = 0; j < 4; j++) {
            unsigned h = f2tf(bS[j]);
            Bh[b_k][b_n + j] = h;
            Bl[b_k][b_n + j] = f2tf(bS[j] - __uint_as_float(h));
        }
    };

    float acc[2][4][4];
#pragma unroll
    for (int mi = 0; mi < 2; mi++)
#pragma unroll
        for (int ni = 0; ni < 4; ni++)
#pragma unroll
            for (int r = 0; r < 4; r++) acc[mi][ni][r] = 0.f;

    loadG(0);
    storeS();
    __syncthreads();

    for (int k0 = 0; k0 < K; k0 += GBK) {
        bool more = (k0 + GBK < K);
        if (more) loadG(k0 + GBK);
#pragma unroll
        for (int kk = 0; kk < GBK; kk += 8) {
            unsigned aHf[2][4], aLf[2][4];
#pragma unroll
            for (int mi = 0; mi < 2; mi++) {
                int mr = m0 + mi * 16 + gq;
                aHf[mi][0] = Ah[kk + tg][mr];
                aHf[mi][1] = Ah[kk + tg][mr + 8];
                aHf[mi][2] = Ah[kk + 4 + tg][mr];
                aHf[mi][3] = Ah[kk + 4 + tg][mr + 8];
                aLf[mi][0] = Al[kk + tg][mr];
                aLf[mi][1] = Al[kk + tg][mr + 8];
                aLf[mi][2] = Al[kk + 4 + tg][mr];
                aLf[mi][3] = Al[kk + 4 + tg][mr + 8];
            }
            unsigned bHf[4][2], bLf[4][2];
#pragma unroll
            for (int ni = 0; ni < 4; ni++) {
                int bc = n0 + ni * 8 + gq;
                bHf[ni][0] = Bh[kk + tg][bc];
                bHf[ni][1] = Bh[kk + 4 + tg][bc];
                bLf[ni][0] = Bl[kk + tg][bc];
                bLf[ni][1] = Bl[kk + 4 + tg][bc];
            }
#pragma unroll
            for (int mi = 0; mi < 2; mi++)
#pragma unroll
                for (int ni = 0; ni < 4; ni++) {
                    mma_tf32(acc[mi][ni], aHf[mi], bHf[ni]);
                    mma_tf32(acc[mi][ni], aHf[mi], bLf[ni]);
                    mma_tf32(acc[mi][ni], aLf[mi], bHf[ni]);
                }
        }
        if (more) {
            __syncthreads();
            storeS();
            __syncthreads();
        }
    }

    // epilogue: c0,c1 -> (r0, c..c+1); c2,c3 -> (r0+8, c..c+1)
#pragma unroll
    for (int mi = 0; mi < 2; mi++) {
        int r0 = row0 + m0 + mi * 16 + gq;
#pragma unroll
        for (int ni = 0; ni < 4; ni++) {
            int c = col0 + n0 + ni * 8 + tg * 2;
            if (c < Kn) {
                if (r0 < M) {
                    float2 v = make_float2(acc[mi][ni][0], acc[mi][ni][1]);
                    *(float2*)(g_feat + (size_t)r0 * Kn + c) = v;
                }
                if (r0 + 8 < M) {
                    float2 v = make_float2(acc[mi][ni][2], acc[mi][ni][3]);
                    *(float2*)(g_feat + (size_t)(r0 + 8) * Kn + c) = v;
                }
            }
        }
    }
}

// ---------------- per-node attention projections (el, er) -------------------
__global__ void elr_kernel(const float* __restrict__ al,
                           const float* __restrict__ ar,
                           int F) {
    int w = (blockIdx.x * blockDim.x + threadIdx.x) >> 5;
    int lane = threadIdx.x & 31;
    if (w >= NN) return;
    const float* frow = g_feat + (size_t)w * HH * F;
#pragma unroll
    for (int h = 0; h < HH; h++) {
        float sl = 0.f, sr = 0.f;
        for (int d = lane; d < F; d += 32) {
            float f = frow[h * F + d];
            sl = fmaf(f, al[h * F + d], sl);
            sr = fmaf(f, ar[h * F + d], sr);
        }
        sl = warpsum(sl);
        sr = warpsum(sr);
        if (lane == 0) {
            g_el[w * HH + h] = sl;
            g_er[w * HH + h] = sr;
        }
    }
}

// ---------------- fused softmax + aggregation, layers 1/2 (HF=128) ----------
#define NCH 4
__global__ void aggr128_kernel(const float* __restrict__ bias) {
    int node = (blockIdx.x * blockDim.x + threadIdx.x) >> 5;
    int lane = threadIdx.x & 31;
    if (node >= NN) return;
    int beg = g_off[node], end = g_off[node + 1];
    int deg = end - beg;
    float4 er4 = *(const float4*)(g_er + (size_t)node * 4);

    int   sc[NCH];
    float x0c[NCH], x1c[NCH], x2c[NCH], x3c[NCH];
    float d0 = 0.f, d1 = 0.f, d2 = 0.f, d3 = 0.f;
    int nch = (deg + 31) >> 5; if (nch > NCH) nch = NCH;

#pragma unroll
    for (int c = 0; c < NCH; c++) {
        sc[c] = 0; x0c[c] = 0.f; x1c[c] = 0.f; x2c[c] = 0.f; x3c[c] = 0.f;
        if (c < nch) {
            int p = beg + c * 32 + lane;
            if (p < end) {
                int s = g_esrc[p]; sc[c] = s;
                float4 el4 = *(const float4*)(g_el + (size_t)s * 4);
                float e0 = __expf(lrelu(el4.x + er4.x));
                float e1 = __expf(lrelu(el4.y + er4.y));
                float e2 = __expf(lrelu(el4.z + er4.z));
                float e3 = __expf(lrelu(el4.w + er4.w));
                x0c[c] = e0; x1c[c] = e1; x2c[c] = e2; x3c[c] = e3;
                d0 += e0; d1 += e1; d2 += e2; d3 += e3;
            }
        }
    }
    for (int p = beg + NCH * 32 + lane; p < end; p += 32) {
        int s = g_esrc[p];
        float4 el4 = *(const float4*)(g_el + (size_t)s * 4);
        d0 += __expf(lrelu(el4.x + er4.x));
        d1 += __expf(lrelu(el4.y + er4.y));
        d2 += __expf(lrelu(el4.z + er4.z));
        d3 += __expf(lrelu(el4.w + er4.w));
    }
    d0 = warpsum(d0); d1 = warpsum(d1); d2 = warpsum(d2); d3 = warpsum(d3);
    float i0 = 1.f / d0, i1 = 1.f / d1, i2 = 1.f / d2, i3 = 1.f / d3;
#pragma unroll
    for (int c = 0; c < NCH; c++) {
        x0c[c] *= i0; x1c[c] *= i1; x2c[c] *= i2; x3c[c] *= i3;
    }

    int h = lane >> 3;
    float4 acc = make_float4(0.f, 0.f, 0.f, 0.f);
#pragma unroll
    for (int c = 0; c < NCH; c++) {
        if (c < nch) {
            int cnt = min(32, deg - c * 32);
            for (int j = 0; j < cnt; j++) {
                int sj = __shfl_sync(FULLMASK, sc[c], j);
                float w0 = __shfl_sync(FULLMASK, x0c[c], j);
                float w1 = __shfl_sync(FULLMASK, x1c[c], j);
                float w2 = __shfl_sync(FULLMASK, x2c[c], j);
                float w3 = __shfl_sync(FULLMASK, x3c[c], j);
                float w = h == 0 ? w0 : (h == 1 ? w1 : (h == 2 ? w2 : w3));
                float4 f = *(const float4*)(g_feat + (size_t)sj * HD + lane * 4);
                acc.x = fmaf(w, f.x, acc.x);
                acc.y = fmaf(w, f.y, acc.y);
                acc.z = fmaf(w, f.z, acc.z);
                acc.w = fmaf(w, f.w, acc.w);
            }
        }
    }
    for (int base = beg + NCH * 32; base < end; base += 32) {
        int p = base + lane;
        int cnt = min(32, end - base);
        int s = 0; float x0 = 0.f, x1 = 0.f, x2 = 0.f, x3 = 0.f;
        if (p < end) {
            s = g_esrc[p];
            float4 el4 = *(const float4*)(g_el + (size_t)s * 4);
            x0 = __expf(lrelu(el4.x + er4.x)) * i0;
            x1 = __expf(lrelu(el4.y + er4.y)) * i1;
            x2 = __expf(lrelu(el4.z + er4.z)) * i2;
            x3 = __expf(lrelu(el4.w + er4.w)) * i3;
        }
        for (int j = 0; j < cnt; j++) {
            int sj = __shfl_sync(FULLMASK, s, j);
            float w0 = __shfl_sync(FULLMASK, x0, j);
            float w1 = __shfl_sync(FULLMASK, x1, j);
            float w2 = __shfl_sync(FULLMASK, x2, j);
            float w3 = __shfl_sync(FULLMASK, x3, j);
            float w = h == 0 ? w0 : (h == 1 ? w1 : (h == 2 ? w2 : w3));
            float4 f = *(const float4*)(g_feat + (size_t)sj * HD + lane * 4);
            acc.x = fmaf(w, f.x, acc.x);
            acc.y = fmaf(w, f.y, acc.y);
            acc.z = fmaf(w, f.z, acc.z);
            acc.w = fmaf(w, f.w, acc.w);
        }
    }

    float4 bv = *(const float4*)(bias + lane * 4);
    float4 o;
    o.x = fmaxf(acc.x + bv.x, 0.f);
    o.y = fmaxf(acc.y + bv.y, 0.f);
    o.z = fmaxf(acc.z + bv.z, 0.f);
    o.w = fmaxf(acc.w + bv.w, 0.f);
    *(float4*)(g_hbuf + (size_t)node * HD + lane * 4) = o;
}

// ---------------- fused softmax + aggr + head-mean + log_softmax, layer 3 ---
__global__ void aggr47_final_kernel(const float* __restrict__ b3,
                                    float* __restrict__ out) {
    int node = (blockIdx.x * blockDim.x + threadIdx.x) >> 5;
    int lane = threadIdx.x & 31;
    if (node >= NN) return;
    int beg = g_off[node], end = g_off[node + 1];
    int deg = end - beg;
    float4 er4 = *(const float4*)(g_er + (size_t)node * 4);

    int   sc[NCH];
    float x0c[NCH], x1c[NCH], x2c[NCH], x3c[NCH];
    float d0 = 0.f, d1 = 0.f, d2 = 0.f, d3 = 0.f;
    int nch = (deg + 31) >> 5; if (nch > NCH) nch = NCH;

#pragma unroll
    for (int c = 0; c < NCH; c++) {
        sc[c] = 0; x0c[c] = 0.f; x1c[c] = 0.f; x2c[c] = 0.f; x3c[c] = 0.f;
        if (c < nch) {
            int p = beg + c * 32 + lane;
            if (p < end) {
                int s = g_esrc[p]; sc[c] = s;
                float4 el4 = *(const float4*)(g_el + (size_t)s * 4);
                float e0 = __expf(lrelu(el4.x + er4.x));
                float e1 = __expf(lrelu(el4.y + er4.y));
                float e2 = __expf(lrelu(el4.z + er4.z));
                float e3 = __expf(lrelu(el4.w + er4.w));
                x0c[c] = e0; x1c[c] = e1; x2c[c] = e2; x3c[c] = e3;
                d0 += e0; d1 += e1; d2 += e2; d3 += e3;
            }
        }
    }
    for (int p = beg + NCH * 32 + lane; p < end; p += 32) {
        int s = g_esrc[p];
        float4 el4 = *(const float4*)(g_el + (size_t)s * 4);
        d0 += __expf(lrelu(el4.x + er4.x));
        d1 += __expf(lrelu(el4.y + er4.y));
        d2 += __expf(lrelu(el4.z + er4.z));
        d3 += __expf(lrelu(el4.w + er4.w));
    }
    d0 = warpsum(d0); d1 = warpsum(d1); d2 = warpsum(d2); d3 = warpsum(d3);
    float i0 = 1.f / d0, i1 = 1.f / d1, i2 = 1.f / d2, i3 = 1.f / d3;
#pragma unroll
    for (int c = 0; c < NCH; c++) {
        x0c[c] *= i0; x1c[c] *= i1; x2c[c] *= i2; x3c[c] *= i3;
    }

    float a0 = 0.f, a1 = 0.f;
#pragma unroll
    for (int c = 0; c < NCH; c++) {
        if (c < nch) {
            int cnt = min(32, deg - c * 32);
            for (int j = 0; j < cnt; j++) {
                int sj = __shfl_sync(FULLMASK, sc[c], j);
                float w0 = __shfl_sync(FULLMASK, x0c[c], j);
                float w1 = __shfl_sync(FULLMASK, x1c[c], j);
                float w2 = __shfl_sync(FULLMASK, x2c[c], j);
                float w3 = __shfl_sync(FULLMASK, x3c[c], j);
                const float* fr = g_feat + (size_t)sj * HC;
                a0 += w0 * fr[lane] + w1 * fr[CC + lane]
                    + w2 * fr[2 * CC + lane] + w3 * fr[3 * CC + lane];
                if (lane < CC - 32) {
                    int cx = 32 + lane;
                    a1 += w0 * fr[cx] + w1 * fr[CC + cx]
                        + w2 * fr[2 * CC + cx] + w3 * fr[3 * CC + cx];
                }
            }
        }
    }
    for (int base = beg + NCH * 32; base < end; base += 32) {
        int p = base + lane;
        int cnt = min(32, end - base);
        int s = 0; float x0 = 0.f, x1 = 0.f, x2 = 0.f, x3 = 0.f;
        if (p < end) {
            s = g_esrc[p];
            float4 el4 = *(const float4*)(g_el + (size_t)s * 4);
            x0 = __expf(lrelu(el4.x + er4.x)) * i0;
            x1 = __expf(lrelu(el4.y + er4.y)) * i1;
            x2 = __expf(lrelu(el4.z + er4.z)) * i2;
            x3 = __expf(lrelu(el4.w + er4.w)) * i3;
        }
        for (int j = 0; j < cnt; j++) {
            int sj = __shfl_sync(FULLMASK, s, j);
            float w0 = __shfl_sync(FULLMASK, x0, j);
            float w1 = __shfl_sync(FULLMASK, x1, j);
            float w2 = __shfl_sync(FULLMASK, x2, j);
            float w3 = __shfl_sync(FULLMASK, x3, j);
            const float* fr = g_feat + (size_t)sj * HC;
            a0 += w0 * fr[lane] + w1 * fr[CC + lane]
                + w2 * fr[2 * CC + lane] + w3 * fr[3 * CC + lane];
            if (lane < CC - 32) {
                int cx = 32 + lane;
                a1 += w0 * fr[cx] + w1 * fr[CC + cx]
                    + w2 * fr[2 * CC + cx] + w3 * fr[3 * CC + cx];
            }
        }
    }

    float v0 = a0 * 0.25f + 0.25f * (b3[lane] + b3[CC + lane] +
                                     b3[2 * CC + lane] + b3[3 * CC + lane]);
    float v1 = 0.f;
    if (lane < CC - 32) {
        int cx = 32 + lane;
        v1 = a1 * 0.25f + 0.25f * (b3[cx] + b3[CC + cx] +
                                   b3[2 * CC + cx] + b3[3 * CC + cx]);
    }
    float mm = v0;
    if (lane < CC - 32) mm = fmaxf(mm, v1);
    mm = warpmax(mm);
    float s = __expf(v0 - mm);
    if (lane < CC - 32) s += __expf(v1 - mm);
    s = warpsum(s);
    float lse = logf(s) + mm;
    out[(size_t)node * CC + lane] = v0 - lse;
    if (lane < CC - 32) out[(size_t)node * CC + 32 + lane] = v1 - lse;
}

// ---------------- host orchestration ----------------------------------------
extern "C" void kernel_launch(void* const* d_in, const int* in_sizes, int n_in,
                              void* d_out, int out_size) {
    const float* x   = (const float*)d_in[0];
    const int*   src = (const int*)  d_in[1];
    const int*   dst = (const int*)  d_in[2];
    const float* W1  = (const float*)d_in[3];
    const float* al1 = (const float*)d_in[4];
    const float* ar1 = (const float*)d_in[5];
    const float* b1  = (const float*)d_in[6];
    const float* W2  = (const float*)d_in[7];
    const float* al2 = (const float*)d_in[8];
    const float* ar2 = (const float*)d_in[9];
    const float* b2  = (const float*)d_in[10];
    const float* W3  = (const float*)d_in[11];
    const float* al3 = (const float*)d_in[12];
    const float* ar3 = (const float*)d_in[13];
    const float* b3  = (const float*)d_in[14];
    float* out = (float*)d_out;

    // ---- CSR build (same graph for all 3 layers) ----
    zero_deg_kernel<<<(NN + 255) / 256, 256>>>();
    hist_kernel<<<(EE + 255) / 256, 256>>>(dst);
    scan_kernel<<<1, 1024>>>();
    scatter_kernel<<<(EE + 255) / 256, 256>>>(src, dst);

    int node_warp_blocks = (NN * 32 + 255) / 256;
    int mblocks = (NN + GBM - 1) / GBM;

    // ---- Layer 1: IN -> H*D, ReLU ----
    tf32_gemm_kernel<<<dim3(2, mblocks), 256>>>(x, W1, NN, IN_F, HD, 0);
    elr_kernel<<<node_warp_blocks, 256>>>(al1, ar1, DD);
    aggr128_kernel<<<node_warp_blocks, 256>>>(b1);

    // ---- Layer 2: H*D -> H*D, ReLU ----
    tf32_gemm_kernel<<<dim3(2, mblocks), 256>>>(nullptr, W2, NN, HD, HD, 1);
    elr_kernel<<<node_warp_blocks, 256>>>(al2, ar2, DD);
    aggr128_kernel<<<node_warp_blocks, 256>>>(b2);

    // ---- Layer 3: H*D -> H*C, head-mean + log_softmax ----
    tf32_gemm_kernel<<<dim3(3, mblocks), 256>>>(nullptr, W3, NN, HD, HC, 1);
    elr_kernel<<<node_warp_blocks, 256>>>(al3, ar3, CC);
    aggr47_final_kernel<<<node_warp_blocks, 256>>>(b3, out);
}